// round 1
// baseline (speedup 1.0000x reference)
#include <cuda_runtime.h>
#include <math.h>

// Problem constants (fixed by setup_inputs)
#define BB 32
#define CC 256
#define NN 64
#define SS 64
#define PP 2080          // upper-tri proposals of 64x64
#define N2 4096          // NN*NN
#define TQ_INV 10.0f     // 1/T_Q
#define TV_INV 10.0f     // 1/T_V
#define EPSN 1e-12f

// Scratch (device globals: no allocation allowed)
__device__ float g_sfT[CC * SS];     // normalized sentence feats, [c][s]
__device__ int   g_ij[PP];           // proposal p -> flat (i*64+j)
__device__ int   g_videoOf[SS];      // sentence -> video
__device__ float g_negsum[SS];       // inter-query masked exp-sum per sentence
__device__ float g_all[SS * SS];     // inter-video score matrix
__device__ int   g_topk_ij[SS];      // top-1 proposal flat index per sentence

// ---------------------------------------------------------------------------
__global__ void k_init(const int* __restrict__ num_targets) {
    int tid = threadIdx.x;
    if (tid < SS) g_negsum[tid] = 0.f;
    if (tid == 0) {
        int s = 0;
        for (int b = 0; b < BB; b++) {
            int n = num_targets[b];
            for (int k = 0; k < n && s < SS; k++) g_videoOf[s++] = b;
        }
        for (; s < SS; s++) g_videoOf[s] = BB - 1;
    }
    for (int idx = tid; idx < N2; idx += blockDim.x) {
        int i = idx >> 6, j = idx & 63;
        if (j >= i) {
            int p = i * NN - (i * (i - 1)) / 2 + (j - i);
            g_ij[p] = idx;
        }
    }
}

// ---------------------------------------------------------------------------
__global__ void k_sfnorm(const float* __restrict__ sents) {
    __shared__ float red[256];
    int s = blockIdx.x, c = threadIdx.x;
    float x = sents[s * CC + c];
    red[c] = x * x;
    __syncthreads();
    for (int o = 128; o > 0; o >>= 1) {
        if (c < o) red[c] += red[c + o];
        __syncthreads();
    }
    float inv = 1.f / fmaxf(sqrtf(red[0]), EPSN);
    g_sfT[c * SS + s] = x * inv;   // transposed store for coalesced GEMM loads
}

// ---------------------------------------------------------------------------
__global__ void k_argmax(const float* __restrict__ iou) {
    __shared__ float vmax[256];
    __shared__ int vidx[256];
    int s = blockIdx.x, tid = threadIdx.x;
    float best = -1e30f; int bi = 0;
    for (int p = tid; p < PP; p += 256) {
        float v = iou[s * N2 + g_ij[p]];
        if (v > best) { best = v; bi = p; }
    }
    vmax[tid] = best; vidx[tid] = bi;
    __syncthreads();
    for (int o = 128; o > 0; o >>= 1) {
        if (tid < o) {
            if (vmax[tid + o] > vmax[tid] ||
                (vmax[tid + o] == vmax[tid] && vidx[tid + o] < vidx[tid])) {
                vmax[tid] = vmax[tid + o];
                vidx[tid] = vidx[tid + o];
            }
        }
        __syncthreads();
    }
    if (tid == 0) g_topk_ij[s] = g_ij[vidx[0]];
}

// ---------------------------------------------------------------------------
__global__ void k_intervideo(const float* __restrict__ video) {
    __shared__ float tv[CC];
    __shared__ float red[256];
    __shared__ float part[4][64];
    int s = blockIdx.x, tid = threadIdx.x;
    int b = g_videoOf[s], ij = g_topk_ij[s];
    float x = video[(long)(b * CC + tid) * N2 + ij];
    tv[tid] = x; red[tid] = x * x;
    __syncthreads();
    for (int o = 128; o > 0; o >>= 1) {
        if (tid < o) red[tid] += red[tid + o];
        __syncthreads();
    }
    float inv = 1.f / fmaxf(sqrtf(red[0]), EPSN);
    int t = tid >> 2, q = tid & 3;
    float d = 0.f;
    int c0 = q * 64;
    for (int c = c0; c < c0 + 64; c++) d += tv[c] * g_sfT[c * SS + t];
    part[q][t] = d;
    __syncthreads();
    if (q == 0)
        g_all[s * SS + t] = (part[0][t] + part[1][t] + part[2][t] + part[3][t]) * inv;
}

// ---------------------------------------------------------------------------
// Main fused GEMM + norm + masked exp-sum.
// Grid: (ceil(P/64), B). Block: 256 threads -> 4 sent x 4 prop per thread.
#define TILE_P 64
#define CHUNK 32
__global__ void __launch_bounds__(256) k_main(const float* __restrict__ video,
                                              const float* __restrict__ iou) {
    __shared__ float sfs[CHUNK][64];
    __shared__ float vfs[CHUNK][64];
    __shared__ int   sij[TILE_P];
    __shared__ float ssqs[4][64];
    __shared__ float sinv[64];
    __shared__ float sred[64];

    int tid = threadIdx.x;
    int b = blockIdx.y;
    int pbase = blockIdx.x * TILE_P;

    if (tid < TILE_P) {
        int pg = pbase + tid;
        sij[tid] = (pg < PP) ? g_ij[pg] : -1;
        sred[tid] = 0.f;
    }
    __syncthreads();

    int ts = tid & 15;   // sentence group: s = ts*4 + 0..3
    int tp = tid >> 4;   // proposal group: p = tp*4 + 0..3

    float acc[4][4];
#pragma unroll
    for (int i = 0; i < 4; i++)
#pragma unroll
        for (int j = 0; j < 4; j++) acc[i][j] = 0.f;

    // loader mapping: fixed proposal per thread, 4 c-groups
    int lp = tid & 63;
    int cg = tid >> 6;
    int lij = sij[lp];
    float ssq = 0.f;
    const float* vb = video + (long)b * CC * N2;

    for (int c0 = 0; c0 < CC; c0 += CHUNK) {
        __syncthreads();
#pragma unroll
        for (int k = 0; k < 8; k++) {
            int cl = cg + 4 * k;                 // 0..31
            float x = (lij >= 0) ? vb[(long)(c0 + cl) * N2 + lij] : 0.f;
            vfs[cl][lp] = x;
            ssq += x * x;
            sfs[cl][lp] = g_sfT[(c0 + cl) * SS + lp];
        }
        __syncthreads();
#pragma unroll
        for (int c = 0; c < CHUNK; c++) {
            float4 a = *(const float4*)&sfs[c][ts * 4];
            float4 v = *(const float4*)&vfs[c][tp * 4];
            acc[0][0] += a.x * v.x; acc[0][1] += a.x * v.y;
            acc[0][2] += a.x * v.z; acc[0][3] += a.x * v.w;
            acc[1][0] += a.y * v.x; acc[1][1] += a.y * v.y;
            acc[1][2] += a.y * v.z; acc[1][3] += a.y * v.w;
            acc[2][0] += a.z * v.x; acc[2][1] += a.z * v.y;
            acc[2][2] += a.z * v.z; acc[2][3] += a.z * v.w;
            acc[3][0] += a.w * v.x; acc[3][1] += a.w * v.y;
            acc[3][2] += a.w * v.z; acc[3][3] += a.w * v.w;
        }
    }

    // per-proposal inverse norm (fused, no second pass over video feats)
    ssqs[cg][lp] = ssq;
    __syncthreads();
    if (tid < 64)
        sinv[tid] = 1.f / fmaxf(sqrtf(ssqs[0][tid] + ssqs[1][tid] +
                                      ssqs[2][tid] + ssqs[3][tid]), EPSN);
    __syncthreads();

    int vOf[4];
#pragma unroll
    for (int k = 0; k < 4; k++) vOf[k] = g_videoOf[ts * 4 + k];

    float lsum[4] = {0.f, 0.f, 0.f, 0.f};
#pragma unroll
    for (int pp = 0; pp < 4; pp++) {
        int p = tp * 4 + pp;
        int ij = sij[p];
        if (ij < 0) continue;
        float inv = sinv[p];
#pragma unroll
        for (int ssn = 0; ssn < 4; ssn++) {
            int s = ts * 4 + ssn;
            float score = acc[ssn][pp] * inv;
            bool neg = true;
            if (vOf[ssn] == b) {
                if (iou[s * N2 + ij] > 0.5f) neg = false;
            }
            if (neg) lsum[ssn] += expf(score * TQ_INV);
        }
    }
#pragma unroll
    for (int ssn = 0; ssn < 4; ssn++)
        atomicAdd(&sred[ts * 4 + ssn], lsum[ssn]);
    __syncthreads();
    if (tid < 64) atomicAdd(&g_negsum[tid], sred[tid]);
}

// ---------------------------------------------------------------------------
__global__ void k_final(float* __restrict__ out) {
    __shared__ float rv[SS], rq[SS];
    int s = threadIdx.x;
    float pos = g_all[s * SS + s];
    float sum = 0.f;
    for (int t = 0; t < SS; t++)
        if (t != s) sum += expf(g_all[s * SS + t] * TV_INV);
    float pv = pos * TV_INV;
    rv[s] = -(pv - logf(expf(pv) + sum));
    float pq = pos * TQ_INV;
    rq[s] = -(pq - logf(expf(pq) + g_negsum[s]));
    __syncthreads();
    if (s == 0) {
        float a = 0.f, bq = 0.f;
        for (int t = 0; t < SS; t++) { a += rv[t]; bq += rq[t]; }
        out[0] = a / SS;
        out[1] = bq / SS;
    }
}

// ---------------------------------------------------------------------------
extern "C" void kernel_launch(void* const* d_in, const int* in_sizes, int n_in,
                              void* d_out, int out_size) {
    const float* video = (const float*)d_in[0];   // [B,C,N,N] f32
    const float* sents = (const float*)d_in[1];   // [S,C] f32
    const int*   ntgt  = (const int*)d_in[2];     // [B] i32
    const float* iou   = (const float*)d_in[3];   // [S,N,N] f32
    float* out = (float*)d_out;

    k_init<<<1, 256>>>(ntgt);
    k_sfnorm<<<SS, 256>>>(sents);
    k_argmax<<<SS, 256>>>(iou);
    k_intervideo<<<SS, 256>>>(video);
    dim3 grid((PP + TILE_P - 1) / TILE_P, BB);
    k_main<<<grid, 256>>>(video, iou);
    k_final<<<1, SS>>>(out);
}

// round 4
// speedup vs baseline: 1.0450x; 1.0450x over previous
#include <cuda_runtime.h>
#include <cuda_bf16.h>
#include <cstdint>
#include <math.h>

#define BB 32
#define SS 64
#define CC 256
#define N2 4096

// smem layout (bytes from dynamic smem base)
#define SM_AHI   0        // 64 x 256 bf16, swizzled rows of 512B  (32KB)
#define SM_ALO   32768    // (32KB)
#define SM_BHI   65536    // 128 x 64 bf16 chunk, swizzled rows of 128B (16KB)
#define SM_BLO   81920    // (16KB)
#define SM_SSQ   98304    // 256 f32
#define SM_SINV  99328    // 128 f32
#define SM_NEG   99840    // 64 f32
#define SM_CAPC  100096
#define SM_CAPS  100112   // 64 int
#define SM_CAPP  100368   // 64 int
#define SMEM_TOTAL 100640

__device__ int   g_videoOf[SS];
__device__ int   g_topk[SS];
__device__ float g_negsum[SS];
__device__ float g_all[SS * SS];
__device__ uint4 g_Afrag[4096];   // 64KB: hi image [0,32768), lo image [32768,65536)

__device__ __forceinline__ uint32_t smem_u32(const void* p) {
    uint32_t a;
    asm("{ .reg .u64 t; cvta.to.shared.u64 t, %1; cvt.u32.u64 %0, t; }" : "=r"(a) : "l"(p));
    return a;
}

#define LDSM4(r0, r1, r2, r3, addr) \
    asm volatile("ldmatrix.sync.aligned.m8n8.x4.shared.b16 {%0,%1,%2,%3}, [%4];" \
                 : "=r"(r0), "=r"(r1), "=r"(r2), "=r"(r3) : "r"(addr))

#define MMA16816(d, a0, a1, a2, a3, b0, b1) \
    asm volatile("mma.sync.aligned.m16n8k16.row.col.f32.bf16.bf16.f32 " \
                 "{%0,%1,%2,%3}, {%4,%5,%6,%7}, {%8,%9}, {%0,%1,%2,%3};" \
                 : "+f"((d)[0]), "+f"((d)[1]), "+f"((d)[2]), "+f"((d)[3]) \
                 : "r"(a0), "r"(a1), "r"(a2), "r"(a3), "r"(b0), "r"(b1))

// ---------------------------------------------------------------------------
// k_prep: bid<64: sentence normalize -> split-bf16 A image (ldmatrix swizzle);
//         bid in [64,128): per-sentence iou argmax over valid proposals;
//         bid==128: videoOf + negsum init.
__global__ void k_prep(const float* __restrict__ sents, const float* __restrict__ iou,
                       const int* __restrict__ ntgt) {
    int bid = blockIdx.x, tid = threadIdx.x;
    if (bid < 64) {
        __shared__ float red[256];
        int s = bid, c = tid;
        float x = sents[s * CC + c];
        red[c] = x * x;
        __syncthreads();
        for (int o = 128; o > 0; o >>= 1) {
            if (c < o) red[c] += red[c + o];
            __syncthreads();
        }
        float inv = 1.f / fmaxf(sqrtf(red[0]), 1e-12f);
        float xn = x * inv;
        __nv_bfloat16 h = __float2bfloat16(xn);
        __nv_bfloat16 l = __float2bfloat16(xn - __bfloat162float(h));
        // A row = 512B (256 k * 2B); 16B unit u = c>>3, swizzled u^(s&7)
        int off = s * 512 + (((c >> 3) ^ (s & 7)) << 4) + (c & 7) * 2;
        char* ab = (char*)g_Afrag;
        *(__nv_bfloat16*)(ab + off) = h;
        *(__nv_bfloat16*)(ab + 32768 + off) = l;
    } else if (bid < 128) {
        int s = bid - 64;
        __shared__ float vmax[256];
        __shared__ int vidx[256];
        float best = -1.f;
        int bi = 0;
        for (int ij = tid; ij < N2; ij += 256) {
            if ((ij & 63) >= (ij >> 6)) {
                float v = iou[s * N2 + ij];
                if (v > best) { best = v; bi = ij; }
            }
        }
        vmax[tid] = best; vidx[tid] = bi;
        __syncthreads();
        for (int o = 128; o > 0; o >>= 1) {
            if (tid < o) {
                if (vmax[tid + o] > vmax[tid] ||
                    (vmax[tid + o] == vmax[tid] && vidx[tid + o] < vidx[tid])) {
                    vmax[tid] = vmax[tid + o];
                    vidx[tid] = vidx[tid + o];
                }
            }
            __syncthreads();
        }
        if (tid == 0) g_topk[s] = vidx[0];
    } else {
        if (tid < SS) g_negsum[tid] = 0.f;
        if (tid == 0) {
            int s = 0;
            for (int b = 0; b < BB; b++) {
                int n = ntgt[b];
                for (int k = 0; k < n && s < SS; k++) g_videoOf[s++] = b;
            }
            for (; s < SS; s++) g_videoOf[s] = BB - 1;
        }
    }
}

// ---------------------------------------------------------------------------
// k_main: per (proposal-tile t, video b). Triangular fragment skipping.
__global__ void __launch_bounds__(256, 2) k_main(const float* __restrict__ video,
                                                 const float* __restrict__ iou) {
    extern __shared__ __align__(128) char sm[];
    uint32_t sb = smem_u32(sm);
    int tid = threadIdx.x;
    int t = blockIdx.x, b = blockIdx.y;
    int ij0 = t * 128, i0 = 2 * t;
    int fmin0 = i0 >> 3, fmin1 = (i0 + 1) >> 3;
    int pstart0 = fmin0 * 8, pstart1 = 64 + fmin1 * 8;

    float* ssq  = (float*)(sm + SM_SSQ);
    float* sinv = (float*)(sm + SM_SINV);
    float* sneg = (float*)(sm + SM_NEG);
    int* capc = (int*)(sm + SM_CAPC);
    int* caps = (int*)(sm + SM_CAPS);
    int* capp = (int*)(sm + SM_CAPP);

    // broadcast-copy prebuilt A (hi+lo, 64KB)
    {
        uint4* d = (uint4*)sm;
#pragma unroll
        for (int r = 0; r < 16; r++) d[tid + r * 256] = g_Afrag[tid + r * 256];
    }
    if (tid == 0) *capc = 0;
    if (tid < 64) sneg[tid] = 0.f;
    __syncthreads();
    // capture list: sentences of this video whose topk proposal is in this tile
    if (tid < 64) {
        int s = tid;
        if (g_videoOf[s] == b) {
            int tk = g_topk[s];
            if (tk >= ij0 && tk < ij0 + 128) {
                int c = atomicAdd(capc, 1);
                caps[c] = s;
                capp[c] = tk - ij0;
            }
        }
    }

    int lane = tid & 31, w = tid >> 5;
    int mrow = (w >> 1) * 16;      // warp's 16 sentence rows
    int nh = w & 1;                // warp's 64-col half
    int fmin = nh ? fmin1 : fmin0;
    int pb = nh * 64;

    // conversion mapping: thread = (prop, c-half)
    int p = tid & 127, half = tid >> 7;
    bool active = (p < 64) ? (p >= pstart0) : (p >= pstart1);
    const float* vptr = video + (size_t)b * CC * N2 + ij0 + p;
    char* Bh = sm + SM_BHI + p * 128;
    char* Bl = sm + SM_BLO + p * 128;
    int psw = p & 7;
    float myssq = 0.f;

    // ldmatrix lane address components (x4: lanes 0-7 tile0, 8-15 tile1, ...)
    int g = lane >> 3, r = lane & 7;
    int am = mrow + ((g & 1) << 3) + r;       // A tiles: m0k0, m8k0, m0k8, m8k8
    uint32_t Abase_m = sb + SM_AHI + am * 512;
    int am7 = am & 7;
    int akoff = (g >> 1) << 3;
    int pB = pb + ((g & 1) << 3) + r;         // B tiles: n0k0, n8k0, n0k8, n8k8
    uint32_t Bbase_p = sb + SM_BHI + pB * 128;
    int pB7 = pB & 7;
    int bkoff = (g >> 1) << 3;

    float acc[32];
#pragma unroll
    for (int i = 0; i < 32; i++) acc[i] = 0.f;

    for (int ch = 0; ch < 4; ch++) {
        if (active) {
            const float* src = vptr + (size_t)(ch * 64 + half * 32) * N2;
#pragma unroll
            for (int k = 0; k < 32; k += 2) {
                float x0 = src[(size_t)k * N2];
                float x1 = src[(size_t)(k + 1) * N2];
                myssq += x0 * x0 + x1 * x1;
                __nv_bfloat16 h0 = __float2bfloat16(x0), h1 = __float2bfloat16(x1);
                __nv_bfloat16 l0 = __float2bfloat16(x0 - __bfloat162float(h0));
                __nv_bfloat16 l1 = __float2bfloat16(x1 - __bfloat162float(h1));
                uint32_t hw = ((uint32_t)__bfloat16_as_ushort(h1) << 16) | __bfloat16_as_ushort(h0);
                uint32_t lw = ((uint32_t)__bfloat16_as_ushort(l1) << 16) | __bfloat16_as_ushort(l0);
                int cl = half * 32 + k;
                int off = (((cl >> 3) ^ psw) << 4) + (cl & 7) * 2;
                *(uint32_t*)(Bh + off) = hw;
                *(uint32_t*)(Bl + off) = lw;
            }
        }
        __syncthreads();
#pragma unroll
        for (int kk = 0; kk < 4; kk++) {
            int kA = ch * 64 + kk * 16 + akoff;
            uint32_t aadr = Abase_m + (((kA >> 3) ^ am7) << 4);
            uint32_t ah0, ah1, ah2, ah3, al0, al1, al2, al3;
            LDSM4(ah0, ah1, ah2, ah3, aadr);
            LDSM4(al0, al1, al2, al3, aadr + 32768);
            int kB = kk * 16 + bkoff;
            uint32_t bsw = (((kB >> 3) ^ pB7) << 4);
#pragma unroll
            for (int fp = 0; fp < 4; fp++) {
                int f = fp * 2;
                if (f + 1 < fmin) continue;
                uint32_t badr = Bbase_p + f * 1024 + bsw;
                uint32_t bh0, bh1, bh2, bh3, bl0, bl1, bl2, bl3;
                LDSM4(bh0, bh1, bh2, bh3, badr);
                LDSM4(bl0, bl1, bl2, bl3, badr + 16384);
                if (f >= fmin) {
                    MMA16816(acc + f * 4, ah0, ah1, ah2, ah3, bh0, bh2);
                    MMA16816(acc + f * 4, ah0, ah1, ah2, ah3, bl0, bl2);
                    MMA16816(acc + f * 4, al0, al1, al2, al3, bh0, bh2);
                }
                MMA16816(acc + f * 4 + 4, ah0, ah1, ah2, ah3, bh1, bh3);
                MMA16816(acc + f * 4 + 4, ah0, ah1, ah2, ah3, bl1, bl3);
                MMA16816(acc + f * 4 + 4, al0, al1, al2, al3, bh1, bh3);
            }
        }
        __syncthreads();
    }

    // per-proposal inverse norms
    ssq[tid] = myssq;
    __syncthreads();
    if (tid < 128)
        sinv[tid] = rsqrtf(fmaxf(ssq[tid] + ssq[tid + 128], 1e-24f));
    __syncthreads();

    // epilogue: mask + exp-sum + topk capture, straight from D fragments
    int ncap = *capc;
    int s0 = mrow + (lane >> 2), s1 = s0 + 8;
    bool home0 = (g_videoOf[s0] == b), home1 = (g_videoOf[s1] == b);
    const float* iou0 = iou + (size_t)s0 * N2 + ij0;
    const float* iou1 = iou + (size_t)s1 * N2 + ij0;
    float ls0 = 0.f, ls1 = 0.f;
#pragma unroll
    for (int f = 0; f < 8; f++) {
        if (f < fmin) continue;
#pragma unroll
        for (int e = 0; e < 2; e++) {
            int pl = pb + f * 8 + 2 * (lane & 3) + e;
            int ij = ij0 + pl;
            if ((ij & 63) < (ij >> 6)) continue;   // lower triangle: invalid
            float inv = sinv[pl];
            float sc0 = acc[f * 4 + e] * inv;
            float sc1 = acc[f * 4 + 2 + e] * inv;
            if (!(home0 && iou0[pl] > 0.5f)) ls0 += __expf(sc0 * 10.f);
            if (!(home1 && iou1[pl] > 0.5f)) ls1 += __expf(sc1 * 10.f);
            for (int cc = 0; cc < ncap; cc++)
                if (capp[cc] == pl) {
                    g_all[caps[cc] * SS + s0] = sc0;
                    g_all[caps[cc] * SS + s1] = sc1;
                }
        }
    }
    ls0 += __shfl_xor_sync(0xffffffffu, ls0, 1);
    ls0 += __shfl_xor_sync(0xffffffffu, ls0, 2);
    ls1 += __shfl_xor_sync(0xffffffffu, ls1, 1);
    ls1 += __shfl_xor_sync(0xffffffffu, ls1, 2);
    if ((lane & 3) == 0) {
        atomicAdd(&sneg[s0], ls0);
        atomicAdd(&sneg[s1], ls1);
    }
    __syncthreads();
    if (tid < 64) atomicAdd(&g_negsum[tid], sneg[tid]);
}

// ---------------------------------------------------------------------------
__global__ void k_final(float* __restrict__ out) {
    __shared__ float rv[SS], rq[SS];
    int s = threadIdx.x;
    float pos = g_all[s * SS + s];
    float sum = 0.f;
    for (int t = 0; t < SS; t++)
        if (t != s) sum += expf(g_all[s * SS + t] * 10.f);
    float pv = pos * 10.f;
    rv[s] = -(pv - logf(expf(pv) + sum));
    float pq = pos * 10.f;
    rq[s] = -(pq - logf(expf(pq) + g_negsum[s]));
    __syncthreads();
    if (s == 0) {
        float a = 0.f, bq = 0.f;
        for (int t = 0; t < SS; t++) { a += rv[t]; bq += rq[t]; }
        out[0] = a / SS;
        out[1] = bq / SS;
    }
}

// ---------------------------------------------------------------------------
extern "C" void kernel_launch(void* const* d_in, const int* in_sizes, int n_in,
                              void* d_out, int out_size) {
    const float* video = (const float*)d_in[0];
    const float* sents = (const float*)d_in[1];
    const int*   ntgt  = (const int*)d_in[2];
    const float* iou   = (const float*)d_in[3];
    float* out = (float*)d_out;

    cudaFuncSetAttribute(k_main, cudaFuncAttributeMaxDynamicSharedMemorySize, SMEM_TOTAL);

    k_prep<<<129, 256>>>(sents, iou, ntgt);
    k_main<<<dim3(32, BB), 256, SMEM_TOTAL>>>(video, iou);
    k_final<<<1, SS>>>(out);
}

// round 5
// speedup vs baseline: 1.3545x; 1.2961x over previous
#include <cuda_runtime.h>
#include <cuda_fp16.h>
#include <cstdint>
#include <math.h>

#define BB 32
#define SS 64
#define CC 256
#define N2 4096

// smem layout (bytes)
#define SM_A    0        // 64 x 256 fp16, swizzled rows of 512B (32KB)
#define SM_B    32768    // 128 x 64 fp16 chunk, swizzled rows of 128B (16KB)
#define SM_SSQ  49152    // 256 f32
#define SM_SINV 50176    // 128 f32
#define SM_NEG  50688    // 64 f32
#define SM_CAPC 50944
#define SM_CAPS 50960    // 64 int
#define SM_CAPP 51216    // 64 int
#define SM_FLAG 51472
#define SM_RED  51488    // 128 f32 (final reduction scratch)
#define SMEM_TOTAL 52000

__device__ int      g_videoOf[SS];
__device__ int      g_topk[SS];
__device__ float    g_negsum[SS];
__device__ float    g_all[SS * SS];
__device__ uint4    g_Aimg[2048];    // 32KB fp16 A image, ldmatrix-swizzled
__device__ unsigned g_done;

__device__ __forceinline__ uint32_t smem_u32(const void* p) {
    uint32_t a;
    asm("{ .reg .u64 t; cvta.to.shared.u64 t, %1; cvt.u32.u64 %0, t; }" : "=r"(a) : "l"(p));
    return a;
}

#define LDSM4(r0, r1, r2, r3, addr) \
    asm volatile("ldmatrix.sync.aligned.m8n8.x4.shared.b16 {%0,%1,%2,%3}, [%4];" \
                 : "=r"(r0), "=r"(r1), "=r"(r2), "=r"(r3) : "r"(addr))

#define MMAF16(d, a0, a1, a2, a3, b0, b1) \
    asm volatile("mma.sync.aligned.m16n8k16.row.col.f32.f16.f16.f32 " \
                 "{%0,%1,%2,%3}, {%4,%5,%6,%7}, {%8,%9}, {%0,%1,%2,%3};" \
                 : "+f"((d)[0]), "+f"((d)[1]), "+f"((d)[2]), "+f"((d)[3]) \
                 : "r"(a0), "r"(a1), "r"(a2), "r"(a3), "r"(b0), "r"(b1))

// ---------------------------------------------------------------------------
// k_prep: bid<64 = one sentence: normalize -> fp16 A image, then iou argmax.
//         bid==64: videoOf / negsum / g_done init.
__global__ void k_prep(const float* __restrict__ sents, const float* __restrict__ iou,
                       const int* __restrict__ ntgt) {
    int bid = blockIdx.x, tid = threadIdx.x;
    if (bid == 64) {
        if (tid < SS) g_negsum[tid] = 0.f;
        if (tid == 0) {
            g_done = 0u;
            int s = 0;
            for (int b = 0; b < BB; b++) {
                int n = ntgt[b];
                for (int k = 0; k < n && s < SS; k++) g_videoOf[s++] = b;
            }
            for (; s < SS; s++) g_videoOf[s] = BB - 1;
        }
        return;
    }
    int s = bid;
    int lane = tid & 31, w = tid >> 5;
    __shared__ float wsum[8];
    __shared__ float amax[8];
    __shared__ int   aidx[8];

    // --- normalize + fp16 A image ---
    float x = sents[s * CC + tid];
    float q = x * x;
#pragma unroll
    for (int o = 16; o; o >>= 1) q += __shfl_xor_sync(~0u, q, o);
    if (lane == 0) wsum[w] = q;
    __syncthreads();
    float tot = wsum[0] + wsum[1] + wsum[2] + wsum[3] +
                wsum[4] + wsum[5] + wsum[6] + wsum[7];
    float inv = 1.f / fmaxf(sqrtf(tot), 1e-12f);
    __half h = __float2half_rn(x * inv);
    int c = tid;
    int off = s * 512 + (((c >> 3) ^ (s & 7)) << 4) + (c & 7) * 2;
    *(__half*)((char*)g_Aimg + off) = h;

    // --- argmax over valid (upper-tri) iou ---
    float best = -1.f;
    int bi = 0;
    const float* irow = iou + (size_t)s * N2;
#pragma unroll
    for (int k = 0; k < 16; k++) {
        int ij = tid + 256 * k;
        if ((ij & 63) >= (ij >> 6)) {
            float v = irow[ij];
            if (v > best) { best = v; bi = ij; }
        }
    }
#pragma unroll
    for (int o = 16; o; o >>= 1) {
        float ov = __shfl_xor_sync(~0u, best, o);
        int   oi = __shfl_xor_sync(~0u, bi, o);
        if (ov > best || (ov == best && oi < bi)) { best = ov; bi = oi; }
    }
    if (lane == 0) { amax[w] = best; aidx[w] = bi; }
    __syncthreads();
    if (tid == 0) {
        float bb = amax[0]; int ii = aidx[0];
        for (int k = 1; k < 8; k++)
            if (amax[k] > bb || (amax[k] == bb && aidx[k] < ii)) { bb = amax[k]; ii = aidx[k]; }
        g_topk[s] = ii;
    }
}

// ---------------------------------------------------------------------------
// k_main: per (proposal-tile t, video b). fp16 single-MMA, triangular skip,
// fused norms + masked exp epilogue + last-CTA final reduction.
__global__ void __launch_bounds__(256, 3) k_main(const float* __restrict__ video,
                                                 const float* __restrict__ iou,
                                                 float* __restrict__ out) {
    extern __shared__ __align__(128) char sm[];
    uint32_t sb = smem_u32(sm);
    int tid = threadIdx.x;
    int t = blockIdx.x, b = blockIdx.y;
    int ij0 = t * 128, i0 = 2 * t;
    int fmin0 = i0 >> 3, fmin1 = (i0 + 1) >> 3;
    int pstart0 = fmin0 * 8, pstart1 = 64 + fmin1 * 8;

    float* ssq  = (float*)(sm + SM_SSQ);
    float* sinv = (float*)(sm + SM_SINV);
    float* sneg = (float*)(sm + SM_NEG);
    int* capc = (int*)(sm + SM_CAPC);
    int* caps = (int*)(sm + SM_CAPS);
    int* capp = (int*)(sm + SM_CAPP);
    int* flag = (int*)(sm + SM_FLAG);
    float* red = (float*)(sm + SM_RED);

    // broadcast-copy prebuilt fp16 A (32KB)
    {
        uint4* d = (uint4*)sm;
#pragma unroll
        for (int r = 0; r < 8; r++) d[tid + r * 256] = g_Aimg[tid + r * 256];
    }
    if (tid == 0) *capc = 0;
    if (tid < 64) sneg[tid] = 0.f;
    __syncthreads();
    if (tid < 64) {
        int s = tid;
        if (g_videoOf[s] == b) {
            int tk = g_topk[s];
            if (tk >= ij0 && tk < ij0 + 128) {
                int c = atomicAdd(capc, 1);
                caps[c] = s;
                capp[c] = tk - ij0;
            }
        }
    }

    int lane = tid & 31, w = tid >> 5;
    int mrow = (w >> 1) * 16;
    int nh = w & 1;
    int fmin = nh ? fmin1 : fmin0;
    int pb = nh * 64;

    // conversion mapping: thread = (proposal, c-half)
    int p = tid & 127, half = tid >> 7;
    bool active = (p < 64) ? (p >= pstart0) : (p >= pstart1);
    const float* vptr = video + (size_t)b * CC * N2 + ij0 + p;
    char* Brow = sm + SM_B + p * 128;
    int psw = p & 7;
    float myssq = 0.f;

    // ldmatrix lane addressing
    int g = lane >> 3, r = lane & 7;
    int am = mrow + ((g & 1) << 3) + r;
    uint32_t Abase_m = sb + SM_A + am * 512;
    int am7 = am & 7;
    int akoff = (g >> 1) << 3;
    int pB = pb + ((g & 1) << 3) + r;
    uint32_t Bbase_p = sb + SM_B + pB * 128;
    int pB7 = pB & 7;
    int bkoff = (g >> 1) << 3;

    float acc[32];
#pragma unroll
    for (int i = 0; i < 32; i++) acc[i] = 0.f;

    for (int ch = 0; ch < 4; ch++) {
        if (active) {
            const float* src = vptr + (size_t)(ch * 64 + half * 32) * N2;
#pragma unroll
            for (int k = 0; k < 32; k += 2) {
                float x0 = src[(size_t)k * N2];
                float x1 = src[(size_t)(k + 1) * N2];
                myssq += x0 * x0 + x1 * x1;
                __half h0 = __float2half_rn(x0), h1 = __float2half_rn(x1);
                uint32_t hw = ((uint32_t)__half_as_ushort(h1) << 16) | __half_as_ushort(h0);
                int cl = half * 32 + k;
                int off = (((cl >> 3) ^ psw) << 4) + (cl & 7) * 2;
                *(uint32_t*)(Brow + off) = hw;
            }
        }
        __syncthreads();
#pragma unroll
        for (int kk = 0; kk < 4; kk++) {
            int kA = ch * 64 + kk * 16 + akoff;
            uint32_t aadr = Abase_m + (((kA >> 3) ^ am7) << 4);
            uint32_t a0, a1, a2, a3;
            LDSM4(a0, a1, a2, a3, aadr);
            int kB = kk * 16 + bkoff;
            uint32_t bsw = (((kB >> 3) ^ pB7) << 4);
#pragma unroll
            for (int fp = 0; fp < 4; fp++) {
                int f = fp * 2;
                if (f + 1 < fmin) continue;
                uint32_t badr = Bbase_p + f * 1024 + bsw;
                uint32_t b0, b1, b2, b3;
                LDSM4(b0, b1, b2, b3, badr);
                if (f >= fmin) MMAF16(acc + f * 4, a0, a1, a2, a3, b0, b2);
                MMAF16(acc + f * 4 + 4, a0, a1, a2, a3, b1, b3);
            }
        }
        __syncthreads();
    }

    // per-proposal inverse norms
    ssq[tid] = myssq;
    __syncthreads();
    if (tid < 128)
        sinv[tid] = rsqrtf(fmaxf(ssq[tid] + ssq[tid + 128], 1e-24f));
    __syncthreads();

    // epilogue: mask + exp-sum + topk capture
    int ncap = *capc;
    int s0 = mrow + (lane >> 2), s1 = s0 + 8;
    bool home0 = (g_videoOf[s0] == b), home1 = (g_videoOf[s1] == b);
    const float* iou0 = iou + (size_t)s0 * N2 + ij0;
    const float* iou1 = iou + (size_t)s1 * N2 + ij0;
    float ls0 = 0.f, ls1 = 0.f;
#pragma unroll
    for (int f = 0; f < 8; f++) {
        if (f < fmin) continue;
#pragma unroll
        for (int e = 0; e < 2; e++) {
            int pl = pb + f * 8 + 2 * (lane & 3) + e;
            int ij = ij0 + pl;
            if ((ij & 63) < (ij >> 6)) continue;
            float inv = sinv[pl];
            float sc0 = acc[f * 4 + e] * inv;
            float sc1 = acc[f * 4 + 2 + e] * inv;
            if (!(home0 && iou0[pl] > 0.5f)) ls0 += __expf(sc0 * 10.f);
            if (!(home1 && iou1[pl] > 0.5f)) ls1 += __expf(sc1 * 10.f);
            for (int cc = 0; cc < ncap; cc++)
                if (capp[cc] == pl) {
                    g_all[caps[cc] * SS + s0] = sc0;
                    g_all[caps[cc] * SS + s1] = sc1;
                }
        }
    }
    ls0 += __shfl_xor_sync(0xffffffffu, ls0, 1);
    ls0 += __shfl_xor_sync(0xffffffffu, ls0, 2);
    ls1 += __shfl_xor_sync(0xffffffffu, ls1, 1);
    ls1 += __shfl_xor_sync(0xffffffffu, ls1, 2);
    if ((lane & 3) == 0) {
        atomicAdd(&sneg[s0], ls0);
        atomicAdd(&sneg[s1], ls1);
    }
    __syncthreads();
    if (tid < 64) atomicAdd(&g_negsum[tid], sneg[tid]);

    // last-CTA final reduction
    __threadfence();
    __syncthreads();
    if (tid == 0) *flag = (atomicAdd(&g_done, 1u) == (unsigned)(gridDim.x * gridDim.y - 1));
    __syncthreads();
    if (*flag) {
        if (tid < 64) {
            int s = tid;
            float pos = __ldcg(&g_all[s * SS + s]);
            float sum = 0.f;
            for (int u = 0; u < SS; u++)
                if (u != s) sum += expf(__ldcg(&g_all[s * SS + u]) * 10.f);
            float pv = pos * 10.f;
            red[s] = -(pv - logf(expf(pv) + sum));
            red[64 + s] = -(pv - logf(expf(pv) + __ldcg(&g_negsum[s])));
        }
        __syncthreads();
        if (tid == 0) {
            float a = 0.f, bq = 0.f;
            for (int u = 0; u < SS; u++) { a += red[u]; bq += red[64 + u]; }
            out[0] = a / SS;
            out[1] = bq / SS;
        }
    }
}

// ---------------------------------------------------------------------------
extern "C" void kernel_launch(void* const* d_in, const int* in_sizes, int n_in,
                              void* d_out, int out_size) {
    const float* video = (const float*)d_in[0];
    const float* sents = (const float*)d_in[1];
    const int*   ntgt  = (const int*)d_in[2];
    const float* iou   = (const float*)d_in[3];
    float* out = (float*)d_out;

    cudaFuncSetAttribute(k_main, cudaFuncAttributeMaxDynamicSharedMemorySize, SMEM_TOTAL);
    cudaFuncSetAttribute(k_main, cudaFuncAttributePreferredSharedMemoryCarveout, 100);

    k_prep<<<65, 256>>>(sents, iou, ntgt);
    k_main<<<dim3(32, BB), 256, SMEM_TOTAL>>>(video, iou, out);
}

// round 6
// speedup vs baseline: 1.4383x; 1.0619x over previous
#include <cuda_runtime.h>
#include <cuda_fp16.h>
#include <cstdint>
#include <math.h>

#define BB 32
#define SS 64
#define CC 256
#define N2 4096

// smem layout (bytes)
#define SM_A    0        // 64 x 256 fp16, swizzled 512B rows (32KB)
#define SM_B    32768    // 128 x 32ch fp16 sub-chunk, swizzled 128B rows (16KB)
#define SM_S    49152    // 3 staging buffers x 16KB (32ch x 128 props fp32)
#define SM_SSQ  98304    // 256 f32
#define SM_SINV 99328    // 128 f32
#define SM_NEG  99840    // 64 f32
#define SM_CAPC 100096
#define SM_CAPS 100112   // 64 int
#define SM_CAPP 100368   // 64 int
#define SM_FLAG 100624
#define SM_RED  100640   // 128 f32
#define SMEM_TOTAL 101248

__device__ int      g_videoOf[SS];
__device__ int      g_topk[SS];
__device__ float    g_negsum[SS];
__device__ float    g_all[SS * SS];
__device__ uint4    g_Aimg[2048];    // 32KB fp16 A image, ldmatrix-swizzled
__device__ unsigned g_done;

__device__ __forceinline__ uint32_t smem_u32(const void* p) {
    uint32_t a;
    asm("{ .reg .u64 t; cvta.to.shared.u64 t, %1; cvt.u32.u64 %0, t; }" : "=r"(a) : "l"(p));
    return a;
}

#define CP16(dst, src) \
    asm volatile("cp.async.cg.shared.global [%0], [%1], 16;" :: "r"(dst), "l"(src))
#define CP_COMMIT() asm volatile("cp.async.commit_group;")
#define CP_WAIT2()  asm volatile("cp.async.wait_group 2;")

#define LDSM4(r0, r1, r2, r3, addr) \
    asm volatile("ldmatrix.sync.aligned.m8n8.x4.shared.b16 {%0,%1,%2,%3}, [%4];" \
                 : "=r"(r0), "=r"(r1), "=r"(r2), "=r"(r3) : "r"(addr))

#define MMAF16(d, a0, a1, a2, a3, b0, b1) \
    asm volatile("mma.sync.aligned.m16n8k16.row.col.f32.f16.f16.f32 " \
                 "{%0,%1,%2,%3}, {%4,%5,%6,%7}, {%8,%9}, {%0,%1,%2,%3};" \
                 : "+f"((d)[0]), "+f"((d)[1]), "+f"((d)[2]), "+f"((d)[3]) \
                 : "r"(a0), "r"(a1), "r"(a2), "r"(a3), "r"(b0), "r"(b1))

// ---------------------------------------------------------------------------
// k_prep: bid<64 = one sentence: normalize -> fp16 A image + iou argmax.
//         bid==64: videoOf / negsum / g_done init.
__global__ void k_prep(const float* __restrict__ sents, const float* __restrict__ iou,
                       const int* __restrict__ ntgt) {
    int bid = blockIdx.x, tid = threadIdx.x;
    if (bid == 64) {
        if (tid < SS) g_negsum[tid] = 0.f;
        if (tid == 0) {
            g_done = 0u;
            int s = 0;
            for (int b = 0; b < BB; b++) {
                int n = ntgt[b];
                for (int k = 0; k < n && s < SS; k++) g_videoOf[s++] = b;
            }
            for (; s < SS; s++) g_videoOf[s] = BB - 1;
        }
        return;
    }
    int s = bid;
    int lane = tid & 31, w = tid >> 5;
    __shared__ float wsum[8];
    __shared__ float amax[8];
    __shared__ int   aidx[8];

    float x = sents[s * CC + tid];
    float q = x * x;
#pragma unroll
    for (int o = 16; o; o >>= 1) q += __shfl_xor_sync(~0u, q, o);
    if (lane == 0) wsum[w] = q;
    __syncthreads();
    float tot = wsum[0] + wsum[1] + wsum[2] + wsum[3] +
                wsum[4] + wsum[5] + wsum[6] + wsum[7];
    float inv = 1.f / fmaxf(sqrtf(tot), 1e-12f);
    __half h = __float2half_rn(x * inv);
    int c = tid;
    int off = s * 512 + (((c >> 3) ^ (s & 7)) << 4) + (c & 7) * 2;
    *(__half*)((char*)g_Aimg + off) = h;

    float best = -1.f;
    int bi = 0;
    const float* irow = iou + (size_t)s * N2;
#pragma unroll
    for (int k = 0; k < 16; k++) {
        int ij = tid + 256 * k;
        if ((ij & 63) >= (ij >> 6)) {
            float v = irow[ij];
            if (v > best) { best = v; bi = ij; }
        }
    }
#pragma unroll
    for (int o = 16; o; o >>= 1) {
        float ov = __shfl_xor_sync(~0u, best, o);
        int   oi = __shfl_xor_sync(~0u, bi, o);
        if (ov > best || (ov == best && oi < bi)) { best = ov; bi = oi; }
    }
    if (lane == 0) { amax[w] = best; aidx[w] = bi; }
    __syncthreads();
    if (tid == 0) {
        float bb = amax[0]; int ii = aidx[0];
        for (int k = 1; k < 8; k++)
            if (amax[k] > bb || (amax[k] == bb && aidx[k] < ii)) { bb = amax[k]; ii = aidx[k]; }
        g_topk[s] = ii;
    }
}

// ---------------------------------------------------------------------------
// k_main: per (proposal-tile t, video b). cp.async 2-ahead pipelined fp16 MMA.
__global__ void __launch_bounds__(256, 2) k_main(const float* __restrict__ video,
                                                 const float* __restrict__ iou,
                                                 float* __restrict__ out) {
    extern __shared__ __align__(128) char sm[];
    uint32_t sb = smem_u32(sm);
    int tid = threadIdx.x;
    int t = blockIdx.x, b = blockIdx.y;
    int ij0 = t * 128, i0 = 2 * t;
    int f0 = i0 >> 3, f1 = (i0 + 1) >> 3;
    int pstart0 = f0 * 8, pstart1 = 64 + f1 * 8;
    int seg0u = 16 - 2 * f0;              // 16B units in segment 0 per channel row
    int upr = 32 - 2 * (f0 + f1);         // total 16B units per channel row

    float* ssq  = (float*)(sm + SM_SSQ);
    float* sinv = (float*)(sm + SM_SINV);
    float* sneg = (float*)(sm + SM_NEG);
    int* capc = (int*)(sm + SM_CAPC);
    int* caps = (int*)(sm + SM_CAPS);
    int* capp = (int*)(sm + SM_CAPP);
    int* flag = (int*)(sm + SM_FLAG);
    float* red = (float*)(sm + SM_RED);

    // loader mapping: 8 threads per channel row (32 rows per sub-chunk)
    int lch = tid >> 3, lj = tid & 7;
    const float* gch = video + (size_t)b * CC * N2 + ij0 + (size_t)lch * N2;
    uint32_t sdst_row = sb + SM_S + lch * 512;

    // prologue: group0 = A image + sub-chunk 0; group1 = sub-chunk 1
#pragma unroll
    for (int r = 0; r < 8; r++)
        CP16(sb + SM_A + tid * 16 + r * 4096, (const char*)g_Aimg + tid * 16 + r * 4096);
#pragma unroll
    for (int u4 = 0; u4 < 4; u4++) {
        int u = lj + u4 * 8;
        if (u < upr) {
            int prop = (u < seg0u) ? (pstart0 + 4 * u) : (pstart1 + 4 * (u - seg0u));
            CP16(sdst_row + prop * 4, gch + prop);
        }
    }
    CP_COMMIT();
#pragma unroll
    for (int u4 = 0; u4 < 4; u4++) {
        int u = lj + u4 * 8;
        if (u < upr) {
            int prop = (u < seg0u) ? (pstart0 + 4 * u) : (pstart1 + 4 * (u - seg0u));
            CP16(sdst_row + 16384 + prop * 4, gch + 32 * N2 + prop);
        }
    }
    CP_COMMIT();

    if (tid == 0) *capc = 0;
    if (tid < 64) sneg[tid] = 0.f;
    if (tid >= 64 && tid < 128) {
        int s = tid - 64;
        if (g_videoOf[s] == b) {
            int tk = g_topk[s];
            if (tk >= ij0 && tk < ij0 + 128) {
                int c = atomicAdd(capc, 1);
                caps[c] = s;
                capp[c] = tk - ij0;
            }
        }
    }

    int lane = tid & 31, w = tid >> 5;
    int mrow = (w >> 1) * 16;
    int nh = w & 1;
    int fmin = nh ? f1 : f0;
    int pb = nh * 64;

    // conversion mapping: thread = (proposal, 16-ch half of the 32-ch sub-chunk)
    int p = tid & 127, half = tid >> 7;
    bool active = (p < 64) ? (p >= pstart0) : (p >= pstart1);
    char* Brow = sm + SM_B + p * 128;
    int psw = p & 7;
    float myssq = 0.f;

    // ldmatrix lane addressing
    int g = lane >> 3, r = lane & 7;
    int am = mrow + ((g & 1) << 3) + r;
    uint32_t Abase_m = sb + SM_A + am * 512;
    int am7 = am & 7;
    int akoff = (g >> 1) << 3;
    int pB = pb + ((g & 1) << 3) + r;
    uint32_t Bbase_p = sb + SM_B + pB * 128;
    int pB7 = pB & 7;
    int bkoff = (g >> 1) << 3;

    float acc[32];
#pragma unroll
    for (int i = 0; i < 32; i++) acc[i] = 0.f;

    int st = 0;   // ch % 3
    for (int ch = 0; ch < 8; ch++) {
        // issue sub-chunk ch+2 (2-ahead)
        if (ch + 2 < 8) {
            int s2 = ch + 2 - ((ch + 2 >= 3) ? 3 : 0);
            if (ch + 2 >= 6) s2 = ch + 2 - 6;
            uint32_t sd = sdst_row + s2 * 16384;
            const float* gs = gch + (size_t)(ch + 2) * 32 * N2;
#pragma unroll
            for (int u4 = 0; u4 < 4; u4++) {
                int u = lj + u4 * 8;
                if (u < upr) {
                    int prop = (u < seg0u) ? (pstart0 + 4 * u) : (pstart1 + 4 * (u - seg0u));
                    CP16(sd + prop * 4, gs + prop);
                }
            }
        }
        CP_COMMIT();
        CP_WAIT2();             // sub-chunk ch landed
        __syncthreads();

        // convert: staged fp32 -> fp16 B (swizzled) + ssq
        if (active) {
            const char* srow = sm + SM_S + st * 16384 + p * 4;
#pragma unroll
            for (int k = 0; k < 16; k += 2) {
                int cl = half * 16 + k;
                float x0 = *(const float*)(srow + (size_t)cl * 512);
                float x1 = *(const float*)(srow + (size_t)(cl + 1) * 512);
                myssq += x0 * x0 + x1 * x1;
                __half h0 = __float2half_rn(x0), h1 = __float2half_rn(x1);
                uint32_t hw = ((uint32_t)__half_as_ushort(h1) << 16) | __half_as_ushort(h0);
                int off = (((cl >> 3) ^ psw) << 4) + (cl & 7) * 2;
                *(uint32_t*)(Brow + off) = hw;
            }
        }
        __syncthreads();

        // MMA: 2 k-steps of 16 over this 32-ch sub-chunk
#pragma unroll
        for (int kk = 0; kk < 2; kk++) {
            int kA = ch * 32 + kk * 16 + akoff;
            uint32_t aadr = Abase_m + (((kA >> 3) ^ am7) << 4);
            uint32_t a0, a1, a2, a3;
            LDSM4(a0, a1, a2, a3, aadr);
            int kB = kk * 16 + bkoff;
            uint32_t bsw = (((kB >> 3) ^ pB7) << 4);
#pragma unroll
            for (int fp = 0; fp < 4; fp++) {
                int f = fp * 2;
                if (f + 1 < fmin) continue;
                uint32_t badr = Bbase_p + f * 1024 + bsw;
                uint32_t b0, b1, b2, b3;
                LDSM4(b0, b1, b2, b3, badr);
                if (f >= fmin) MMAF16(acc + f * 4, a0, a1, a2, a3, b0, b2);
                MMAF16(acc + f * 4 + 4, a0, a1, a2, a3, b1, b3);
            }
        }
        st = (st == 2) ? 0 : st + 1;
    }
    __syncthreads();

    // per-proposal inverse norms
    ssq[tid] = myssq;
    __syncthreads();
    if (tid < 128)
        sinv[tid] = rsqrtf(fmaxf(ssq[tid] + ssq[tid + 128], 1e-24f));
    __syncthreads();

    // epilogue: mask + exp-sum + topk capture
    int ncap = *capc;
    int s0 = mrow + (lane >> 2), s1 = s0 + 8;
    bool home0 = (g_videoOf[s0] == b), home1 = (g_videoOf[s1] == b);
    const float* iou0 = iou + (size_t)s0 * N2 + ij0;
    const float* iou1 = iou + (size_t)s1 * N2 + ij0;
    float ls0 = 0.f, ls1 = 0.f;
#pragma unroll
    for (int f = 0; f < 8; f++) {
        if (f < fmin) continue;
#pragma unroll
        for (int e = 0; e < 2; e++) {
            int pl = pb + f * 8 + 2 * (lane & 3) + e;
            int ij = ij0 + pl;
            if ((ij & 63) < (ij >> 6)) continue;
            float inv = sinv[pl];
            float sc0 = acc[f * 4 + e] * inv;
            float sc1 = acc[f * 4 + 2 + e] * inv;
            if (!(home0 && iou0[pl] > 0.5f)) ls0 += __expf(sc0 * 10.f);
            if (!(home1 && iou1[pl] > 0.5f)) ls1 += __expf(sc1 * 10.f);
            for (int cc = 0; cc < ncap; cc++)
                if (capp[cc] == pl) {
                    g_all[caps[cc] * SS + s0] = sc0;
                    g_all[caps[cc] * SS + s1] = sc1;
                }
        }
    }
    ls0 += __shfl_xor_sync(0xffffffffu, ls0, 1);
    ls0 += __shfl_xor_sync(0xffffffffu, ls0, 2);
    ls1 += __shfl_xor_sync(0xffffffffu, ls1, 1);
    ls1 += __shfl_xor_sync(0xffffffffu, ls1, 2);
    if ((lane & 3) == 0) {
        atomicAdd(&sneg[s0], ls0);
        atomicAdd(&sneg[s1], ls1);
    }
    __syncthreads();
    if (tid < 64) atomicAdd(&g_negsum[tid], sneg[tid]);

    // last-CTA final reduction
    __threadfence();
    __syncthreads();
    if (tid == 0) *flag = (atomicAdd(&g_done, 1u) == (unsigned)(gridDim.x * gridDim.y - 1));
    __syncthreads();
    if (*flag) {
        if (tid < 64) {
            int s = tid;
            float pos = __ldcg(&g_all[s * SS + s]);
            float sum = 0.f;
            for (int u = 0; u < SS; u++)
                if (u != s) sum += expf(__ldcg(&g_all[s * SS + u]) * 10.f);
            float pv = pos * 10.f;
            red[s] = -(pv - logf(expf(pv) + sum));
            red[64 + s] = -(pv - logf(expf(pv) + __ldcg(&g_negsum[s])));
        }
        __syncthreads();
        if (tid == 0) {
            float a = 0.f, bq = 0.f;
            for (int u = 0; u < SS; u++) { a += red[u]; bq += red[64 + u]; }
            out[0] = a / SS;
            out[1] = bq / SS;
        }
    }
}

// ---------------------------------------------------------------------------
extern "C" void kernel_launch(void* const* d_in, const int* in_sizes, int n_in,
                              void* d_out, int out_size) {
    const float* video = (const float*)d_in[0];
    const float* sents = (const float*)d_in[1];
    const int*   ntgt  = (const int*)d_in[2];
    const float* iou   = (const float*)d_in[3];
    float* out = (float*)d_out;

    cudaFuncSetAttribute(k_main, cudaFuncAttributeMaxDynamicSharedMemorySize, SMEM_TOTAL);
    cudaFuncSetAttribute(k_main, cudaFuncAttributePreferredSharedMemoryCarveout, 100);

    k_prep<<<65, 256>>>(sents, iou, ntgt);
    k_main<<<dim3(32, BB), 256, SMEM_TOTAL>>>(video, iou, out);
}